// round 3
// baseline (speedup 1.0000x reference)
#include <cuda_runtime.h>
#include <math.h>

// Problem constants (fixed shapes for this problem instance)
#define BB    16          // batch
#define TT    50          // targets per batch
#define GG    64          // grid (in_h == in_w == 64 -> scale 8 -> anchors 6..8)
#define NA    3           // local anchors
#define NC    80          // classes
#define ATTR  85          // 5 + NC
#define CELLS (BB*NA*GG*GG)  // 196608

// Anchors / 8 (grid units), all 9
__constant__ float c_aw[9] = {1.25f, 2.0f, 4.125f, 3.75f, 7.75f, 7.375f, 14.5f, 19.5f, 46.625f};
__constant__ float c_ah[9] = {1.625f, 3.75f, 2.875f, 7.625f, 5.625f, 14.875f, 11.25f, 24.75f, 40.75f};

// Scratch (device globals: no allocation allowed)
__device__ float    g_noobj[CELLS];
__device__ int      g_widx[CELLS];        // winner target index + 1 (0 = no hit)
__device__ unsigned g_clsbits[CELLS * 3]; // 80-bit one-hot union per cell
__device__ float    g_acc[9];             // lx,ly,lw,lh,lobj,lnoobj,lcls,n_obj,n_noobj

// ---------------------------------------------------------------------------
__global__ void k_init() {
    int i = blockIdx.x * blockDim.x + threadIdx.x;
    if (i < CELLS) {
        g_noobj[i] = 1.0f;
        g_widx[i] = 0;
        g_clsbits[3*i + 0] = 0u;
        g_clsbits[3*i + 1] = 0u;
        g_clsbits[3*i + 2] = 0u;
    }
    if (i < 9) g_acc[i] = 0.0f;
}

// ---------------------------------------------------------------------------
// One block. Stage gt to SMEM, then thread b walks batch b's targets IN ORDER
// (deterministic last-wins for duplicate-cell "set" scatters). Cross-batch
// cells are disjoint, so plain (non-atomic) RMW is safe.
__global__ void k_scatter(const float* __restrict__ gt) {
    __shared__ float s_gt[BB * TT * 5];
    for (int i = threadIdx.x; i < BB * TT * 5; i += blockDim.x) s_gt[i] = gt[i];
    __syncthreads();

    int b = threadIdx.x;
    if (b >= BB) return;

    for (int t = 0; t < TT; t++) {
        const float* g = &s_gt[(b * TT + t) * 5];
        float x = g[0], y = g[1], w = g[2], h = g[3], c = g[4];
        if (!((x + y + w + h + c) > 0.0f)) continue;  // valid = sum > 0

        float gx = x * GG, gy = y * GG, gw = w * GG, gh = h * GG;
        int gi = (int)gy, gj = (int)gx;

        float iouv[9];
        float best_iou = -1.0f; int best = 0;
        #pragma unroll
        for (int a = 0; a < 9; a++) {
            float inter = fminf(gw, c_aw[a]) * fminf(gh, c_ah[a]);
            float uni   = gw * gh + c_aw[a] * c_ah[a] - inter;
            float iou   = inter / (uni + 1e-16f);
            iouv[a] = iou;
            if (iou > best_iou) { best_iou = iou; best = a; }  // first max wins (argmax)
        }

        bool in_b = (gi >= 0) && (gi < GG) && (gj >= 0) && (gj < GG);

        // noobj clear: local anchors with IOU > 0.5 (order-independent min)
        #pragma unroll
        for (int a = 0; a < NA; a++) {
            if (in_b && iouv[6 + a] > 0.5f) {
                g_noobj[((b * NA + a) * GG + gi) * GG + gj] = 0.0f;
            }
        }

        // hit: best over all 9 anchors is a local one
        if (in_b && best >= 6) {
            int a = best - 6;
            int cell = ((b * NA + a) * GG + gi) * GG + gj;
            g_widx[cell] = t + 1;                       // last-wins (serial in t)
            int ci = (int)c;
            g_clsbits[cell * 3 + (ci >> 5)] |= (1u << (ci & 31));  // union (.max)
        }
    }
}

// ---------------------------------------------------------------------------
__device__ __forceinline__ float sigmoidf(float z) { return 1.0f / (1.0f + expf(-z)); }
__device__ __forceinline__ float bcef(float p, float y) {
    p = fminf(fmaxf(p, 1e-12f), 1.0f - 1e-12f);
    return -(y * logf(p) + (1.0f - y) * logf(1.0f - p));
}

__global__ void k_loss(const float* __restrict__ bb, const float* __restrict__ gt) {
    int cell = blockIdx.x * blockDim.x + threadIdx.x;

    float acc0 = 0.f, acc1 = 0.f, acc2 = 0.f, acc3 = 0.f;
    float acc4 = 0.f, acc5 = 0.f, acc6 = 0.f, acc7 = 0.f, acc8 = 0.f;

    if (cell < CELLS) {
        int b   = cell / (NA * GG * GG);
        int rem = cell % (NA * GG * GG);
        int a   = rem / (GG * GG);
        int ij  = rem % (GG * GG);
        const float* base = bb + (size_t)b * (NA * ATTR * GG * GG)
                               + (size_t)(a * ATTR) * (GG * GG) + ij;

        int widx  = g_widx[cell];
        float msk = widx ? 1.0f : 0.0f;
        float no  = g_noobj[cell];

        float pconf = sigmoidf(base[4 * GG * GG]);
        float bc    = bcef(pconf, msk);   // gt_conf == mask

        acc4 = msk * bc;   // loss_obj numerator
        acc5 = no  * bc;   // loss_noobj numerator
        acc7 = msk;        // n_obj
        acc8 = no;         // n_noobj

        if (widx) {
            int t = widx - 1;
            const float* gr = gt + (b * TT + t) * 5;
            float gx = gr[0] * GG, gy = gr[1] * GG, gw = gr[2] * GG, gh = gr[3] * GG;
            int gi = (int)gy, gj = (int)gx;

            float best_iou = -1.0f; int best = 0;
            #pragma unroll
            for (int k = 0; k < 9; k++) {
                float inter = fminf(gw, c_aw[k]) * fminf(gh, c_ah[k]);
                float uni   = gw * gh + c_aw[k] * c_ah[k] - inter;
                float iou   = inter / (uni + 1e-16f);
                if (iou > best_iou) { best_iou = iou; best = k; }
            }
            float tx = gx - (float)gj;
            float ty = gy - (float)gi;
            float tw = logf(gw / c_aw[best] + 1e-16f);
            float th = logf(gh / c_ah[best] + 1e-16f);

            float sx = sigmoidf(base[0]);
            float sy = sigmoidf(base[GG * GG]);
            float zw = base[2 * GG * GG];
            float zh = base[3 * GG * GG];
            acc0 = (sx - tx) * (sx - tx);
            acc1 = (sy - ty) * (sy - ty);
            acc2 = (zw - tw) * (zw - tw);
            acc3 = (zh - th) * (zh - th);

            unsigned cb0 = g_clsbits[cell * 3 + 0];
            unsigned cb1 = g_clsbits[cell * 3 + 1];
            unsigned cb2 = g_clsbits[cell * 3 + 2];
            float lc = 0.0f;
            #pragma unroll 8
            for (int c = 0; c < NC; c++) {
                unsigned bit = (c < 32) ? ((cb0 >> c) & 1u)
                              : (c < 64) ? ((cb1 >> (c - 32)) & 1u)
                                         : ((cb2 >> (c - 64)) & 1u);
                float pc = sigmoidf(base[(5 + c) * GG * GG]);
                lc += bcef(pc, (float)bit);
            }
            acc6 = lc;
        }
    }

    // warp shuffle reduce -> shared atomics (per warp) -> global atomics (per block)
    #pragma unroll
    for (int off = 16; off > 0; off >>= 1) {
        acc0 += __shfl_down_sync(0xFFFFFFFFu, acc0, off);
        acc1 += __shfl_down_sync(0xFFFFFFFFu, acc1, off);
        acc2 += __shfl_down_sync(0xFFFFFFFFu, acc2, off);
        acc3 += __shfl_down_sync(0xFFFFFFFFu, acc3, off);
        acc4 += __shfl_down_sync(0xFFFFFFFFu, acc4, off);
        acc5 += __shfl_down_sync(0xFFFFFFFFu, acc5, off);
        acc6 += __shfl_down_sync(0xFFFFFFFFu, acc6, off);
        acc7 += __shfl_down_sync(0xFFFFFFFFu, acc7, off);
        acc8 += __shfl_down_sync(0xFFFFFFFFu, acc8, off);
    }

    __shared__ float s_acc[9];
    if (threadIdx.x < 9) s_acc[threadIdx.x] = 0.0f;
    __syncthreads();
    if ((threadIdx.x & 31) == 0) {
        atomicAdd(&s_acc[0], acc0); atomicAdd(&s_acc[1], acc1);
        atomicAdd(&s_acc[2], acc2); atomicAdd(&s_acc[3], acc3);
        atomicAdd(&s_acc[4], acc4); atomicAdd(&s_acc[5], acc5);
        atomicAdd(&s_acc[6], acc6); atomicAdd(&s_acc[7], acc7);
        atomicAdd(&s_acc[8], acc8);
    }
    __syncthreads();
    if (threadIdx.x < 9) atomicAdd(&g_acc[threadIdx.x], s_acc[threadIdx.x]);
}

// ---------------------------------------------------------------------------
__global__ void k_final(float* __restrict__ out) {
    float lx = g_acc[0], ly = g_acc[1], lw = g_acc[2], lh = g_acc[3];
    float lo = g_acc[4], ln = g_acc[5], lc = g_acc[6];
    float n_obj   = fmaxf(g_acc[7], 1.0f);
    float n_noobj = fmaxf(g_acc[8], 1.0f);

    float bbox = 5.0f * ((lx + ly + lw + lh) / n_obj);
    float obj  = 1.0f * (lo / n_obj) + 0.5f * (ln / n_noobj);
    float cls  = 1.0f * (lc / (n_obj * (float)NC));

    out[0] = bbox + obj + cls;
    out[1] = bbox;
    out[2] = obj;
    out[3] = cls;
}

// ---------------------------------------------------------------------------
extern "C" void kernel_launch(void* const* d_in, const int* in_sizes, int n_in,
                              void* d_out, int out_size) {
    const float* backbone = (const float*)d_in[0];  // [16, 255, 64, 64] f32
    const float* gt       = (const float*)d_in[1];  // [16, 50, 5] f32
    float* out            = (float*)d_out;          // 4 f32

    k_init<<<(CELLS + 255) / 256, 256>>>();
    k_scatter<<<1, 256>>>(gt);
    k_loss<<<(CELLS + 255) / 256, 256>>>(backbone, gt);
    k_final<<<1, 1>>>(out);
}

// round 4
// speedup vs baseline: 2.3159x; 2.3159x over previous
#include <cuda_runtime.h>
#include <math.h>

#define BB    16
#define TT    50
#define GG    64
#define NA    3
#define NC    80
#define CELLS (BB*NA*GG*GG)      // 196608
#define NTGT  (BB*TT)            // 800
#define PLANE 4096               // GG*GG
#define BMW   384                // bitmap words per batch (3*4096/32)

#define NB_DENSE  192            // 49152 float4 / 256
#define NB_SPARSE 32             // 256 warps for <=800 winners
#define NB_CLR    12             // 3072 threads for <=2400 cleared
#define NB_TOTAL  (NB_DENSE + NB_SPARSE + NB_CLR)

// Anchors / 8 (grid units)
__constant__ float c_aw[9] = {1.25f, 2.0f, 4.125f, 3.75f, 7.75f, 7.375f, 14.5f, 19.5f, 46.625f};
__constant__ float c_ah[9] = {1.625f, 3.75f, 2.875f, 7.625f, 5.625f, 14.875f, 11.25f, 24.75f, 40.75f};

// Compact global scratch (tiny)
__device__ int   g_nwin, g_nclr, g_bcount;
__device__ int   g_win[NTGT * 6];   // {b<<14|cell, t, bits0, bits1, bits2, cleared}
__device__ int   g_clr[NTGT * 3];   // b<<14|cell
// g_acc: 0 bbox, 1 obj_num, 2 zcorr, 3 cls_num, 4 n_obj, 5 clr_sp, 6 dense_sp
__device__ float g_acc[8];

__device__ __forceinline__ float softplusf(float z) { return __logf(1.0f + __expf(z)); }
__device__ __forceinline__ float sigmf(float z)     { return 1.0f / (1.0f + __expf(-z)); }

// ---------------------------------------------------------------------------
// Kernel A: build cleared bitmap + dedup'd winner list. One block, 256 threads.
__global__ void k_prep(const float* __restrict__ gt) {
    __shared__ unsigned s_bm[BB * BMW];     // 24 KB
    __shared__ int s_cell[NTGT], s_t[NTGT], s_cls[NTGT];   // 9.6 KB
    __shared__ int s_cnt[BB];

    int tid = threadIdx.x;
    if (tid == 0) { g_nwin = 0; g_nclr = 0; g_bcount = 0; }
    if (tid < 8)  g_acc[tid] = 0.0f;
    if (tid < BB) s_cnt[tid] = 0;
    for (int i = tid; i < BB * BMW; i += 256) s_bm[i] = 0u;
    __syncthreads();

    // Phase 1: all targets in parallel
    for (int g = tid; g < NTGT; g += 256) {
        int b = g / TT, t = g % TT;
        const float* r = gt + g * 5;
        float x = r[0], y = r[1], w = r[2], h = r[3], c = r[4];
        if (!((x + y + w + h + c) > 0.0f)) continue;

        float gx = x * GG, gy = y * GG, gw = w * GG, gh = h * GG;
        int gi = (int)gy, gj = (int)gx;
        if (gi < 0 || gi >= GG || gj < 0 || gj >= GG) continue;  // JAX drops OOB scatters

        float best_iou = -1.0f; int best = 0; float iouL[3];
        #pragma unroll
        for (int a = 0; a < 9; a++) {
            float inter = fminf(gw, c_aw[a]) * fminf(gh, c_ah[a]);
            float uni   = gw * gh + c_aw[a] * c_ah[a] - inter;
            float iou   = inter / (uni + 1e-16f);
            if (a >= 6) iouL[a - 6] = iou;
            if (iou > best_iou) { best_iou = iou; best = a; }   // first-max = argmax
        }

        #pragma unroll
        for (int a = 0; a < NA; a++) {
            if (iouL[a] > 0.5f) {
                int cell = a * PLANE + gi * GG + gj;
                atomicOr(&s_bm[b * BMW + (cell >> 5)], 1u << (cell & 31));
            }
        }
        if (best >= 6) {
            int cell = (best - 6) * PLANE + gi * GG + gj;
            int slot = atomicAdd(&s_cnt[b], 1);
            int e = b * TT + slot;
            s_cell[e] = cell; s_t[e] = t; s_cls[e] = (int)c;
        }
    }
    __syncthreads();

    // Phase 2: resolve winners (last-wins by t) + class-bit union + cleared flag
    for (int idx = tid; idx < NTGT; idx += 256) {
        int b = idx / TT, s = idx % TT;
        if (s >= s_cnt[b]) continue;
        int e = b * TT + s;
        int cell = s_cell[e], t = s_t[e];
        bool win = true;
        unsigned b0 = 0, b1 = 0, b2 = 0;
        int n = s_cnt[b];
        for (int j = 0; j < n; j++) {
            int e2 = b * TT + j;
            if (s_cell[e2] == cell) {
                if (s_t[e2] > t) win = false;
                int c = s_cls[e2];
                if (c < 32)      b0 |= 1u << c;
                else if (c < 64) b1 |= 1u << (c - 32);
                else             b2 |= 1u << (c - 64);
            }
        }
        if (win) {
            int cl = (s_bm[b * BMW + (cell >> 5)] >> (cell & 31)) & 1;
            int wslot = atomicAdd(&g_nwin, 1);
            int* W = &g_win[wslot * 6];
            W[0] = (b << 14) | cell; W[1] = t;
            W[2] = (int)b0; W[3] = (int)b1; W[4] = (int)b2; W[5] = cl;
        }
    }

    // Phase 3: bitmap -> cleared list
    for (int wi = tid; wi < BB * BMW; wi += 256) {
        unsigned word = s_bm[wi];
        if (!word) continue;
        int b = wi / BMW, base = (wi % BMW) << 5;
        while (word) {
            int bit = __ffs(word) - 1; word &= word - 1;
            int slot = atomicAdd(&g_nclr, 1);
            g_clr[slot] = (b << 14) | (base + bit);
        }
    }
}

// ---------------------------------------------------------------------------
// Kernel B: dense softplus reduce + sparse winner/cleared processing + finalize.
__global__ void __launch_bounds__(256) k_main(const float* __restrict__ bb,
                                              const float* __restrict__ gt,
                                              float* __restrict__ out) {
    int bid = blockIdx.x, tid = threadIdx.x;
    int lane = tid & 31;
    float local = 0.0f;
    int accIdx = 6;   // dense_sp by default

    if (bid < NB_DENSE) {
        // Dense: sum softplus over all conf logits (48 planes x 4096 floats)
        int idx   = bid * 256 + tid;              // < 49152 float4s
        int plane = idx >> 10;
        int pos   = (idx & 1023) << 2;
        int b = plane / NA, a = plane % NA;
        const float4 v = *(const float4*)(bb + ((size_t)b * 255 + a * 85 + 4) * PLANE + pos);
        local = softplusf(v.x) + softplusf(v.y) + softplusf(v.z) + softplusf(v.w);
    } else if (bid < NB_DENSE + NB_SPARSE) {
        // Sparse winners: one warp per winner cell
        int wid = (bid - NB_DENSE) * 8 + (tid >> 5);
        int nw = g_nwin;
        for (int e = wid; e < nw; e += NB_SPARSE * 8) {
            const int* W = &g_win[e * 6];
            int bc = W[0]; int b = bc >> 14, cell = bc & 16383;
            int t = W[1];
            unsigned bits0 = (unsigned)W[2], bits1 = (unsigned)W[3], bits2 = (unsigned)W[4];
            int cleared = W[5];
            int a = cell >> 12, ij = cell & (PLANE - 1);
            const float* base = bb + ((size_t)b * 255 + a * 85) * PLANE + ij;

            // class BCE over 80 classes, lanes strided
            float cls = 0.0f;
            for (int c = lane; c < NC; c += 32) {
                float z = base[(5 + c) * PLANE];
                unsigned bit = (c < 32) ? ((bits0 >> c) & 1u)
                              : (c < 64) ? ((bits1 >> (c - 32)) & 1u)
                                         : ((bits2 >> (c - 64)) & 1u);
                cls += softplusf(z) - (float)bit * z;
            }
            #pragma unroll
            for (int off = 16; off > 0; off >>= 1)
                cls += __shfl_down_sync(0xFFFFFFFFu, cls, off);

            if (lane == 0) {
                float z0 = base[0], z1 = base[PLANE], z2 = base[2 * PLANE],
                      z3 = base[3 * PLANE], z4 = base[4 * PLANE];
                const float* r = gt + (b * TT + t) * 5;
                float gx = r[0] * GG, gy = r[1] * GG, gw = r[2] * GG, gh = r[3] * GG;
                int gi = (int)gy, gj = (int)gx;
                float best_iou = -1.0f; int best = 0;
                #pragma unroll
                for (int k = 0; k < 9; k++) {
                    float inter = fminf(gw, c_aw[k]) * fminf(gh, c_ah[k]);
                    float uni   = gw * gh + c_aw[k] * c_ah[k] - inter;
                    float iou   = inter / (uni + 1e-16f);
                    if (iou > best_iou) { best_iou = iou; best = k; }
                }
                float tx = gx - (float)gj, ty = gy - (float)gi;
                float tw = __logf(gw / c_aw[best] + 1e-16f);
                float th = __logf(gh / c_ah[best] + 1e-16f);
                float sx = sigmf(z0), sy = sigmf(z1);
                float bbox = (sx - tx) * (sx - tx) + (sy - ty) * (sy - ty)
                           + (z2 - tw) * (z2 - tw) + (z3 - th) * (z3 - th);
                atomicAdd(&g_acc[0], bbox);
                atomicAdd(&g_acc[1], softplusf(z4) - z4);   // obj numerator
                if (!cleared) atomicAdd(&g_acc[2], z4);     // noobj z-correction
                atomicAdd(&g_acc[3], cls);
                atomicAdd(&g_acc[4], 1.0f);                 // n_obj
            }
        }
    } else {
        // Cleared cells: subtract softplus at cleared conf positions
        int nc = g_nclr;
        for (int i = (bid - NB_DENSE - NB_SPARSE) * 256 + tid; i < nc; i += NB_CLR * 256) {
            int bc = g_clr[i]; int b = bc >> 14, cell = bc & 16383;
            int a = cell >> 12, ij = cell & (PLANE - 1);
            float z = bb[((size_t)b * 255 + a * 85 + 4) * PLANE + ij];
            local += softplusf(z);
        }
        accIdx = 5;   // clr_sp
    }

    // Block reduce `local` -> one atomic per warp (sparse branch contributes 0)
    #pragma unroll
    for (int off = 16; off > 0; off >>= 1)
        local += __shfl_down_sync(0xFFFFFFFFu, local, off);
    if (lane == 0 && local != 0.0f) atomicAdd(&g_acc[accIdx], local);

    // Finalize: last block out
    __syncthreads();
    if (tid == 0) {
        __threadfence();
        int old = atomicAdd(&g_bcount, 1);
        if (old == gridDim.x - 1) {
            float n_obj   = fmaxf(g_acc[4], 1.0f);
            float n_noobj = fmaxf((float)CELLS - (float)g_nclr, 1.0f);
            float noobj_num = g_acc[6] - g_acc[5] - g_acc[2];
            float bbox = 5.0f * g_acc[0] / n_obj;
            float obj  = g_acc[1] / n_obj + 0.5f * noobj_num / n_noobj;
            float cls  = g_acc[3] / (n_obj * (float)NC);
            out[0] = bbox + obj + cls;
            out[1] = bbox;
            out[2] = obj;
            out[3] = cls;
        }
    }
}

// ---------------------------------------------------------------------------
extern "C" void kernel_launch(void* const* d_in, const int* in_sizes, int n_in,
                              void* d_out, int out_size) {
    const float* backbone = (const float*)d_in[0];  // [16, 255, 64, 64] f32
    const float* gt       = (const float*)d_in[1];  // [16, 50, 5] f32
    float* out            = (float*)d_out;          // 4 f32

    k_prep<<<1, 256>>>(gt);
    k_main<<<NB_TOTAL, 256>>>(backbone, gt, out);
}